// round 1
// baseline (speedup 1.0000x reference)
#include <cuda_runtime.h>

#define J 24
#define CIN 32
#define COUT 32
#define KS 15
#define PAD 7
#define BB 32
#define TFRAMES 4096
#define TILE_T 128
#define XCOLS 142          // TILE_T + KS - 1
#define XPITCH 144
#define NTHREADS 256

// Preprocessed masked weights, channel-pair packed:
// layout [j(24)][s(3)][cpair(16)][ci(32)][k(15)] float2 = {w[j*32+2cp][i*32+ci][k], w[j*32+2cp+1][...]}
// where i = j-1+s; zero-filled when i is out of range (== topology mask).
__device__ float2 g_wp[J * 3 * 16 * 32 * KS];

__global__ void wprep_kernel(const float* __restrict__ weight) {
    int idx = blockIdx.x * blockDim.x + threadIdx.x;
    const int total = J * 3 * 16 * 32 * KS;
    if (idx >= total) return;
    int r = idx;
    int k  = r % KS;  r /= KS;
    int ci = r % 32;  r /= 32;
    int cp = r % 16;  r /= 16;
    int s  = r % 3;   r /= 3;
    int j  = r;
    int i  = j - 1 + s;
    float2 v = make_float2(0.f, 0.f);
    if (i >= 0 && i < J) {
        int iin = i * CIN + ci;
        int c0  = j * COUT + 2 * cp;
        v.x = weight[((size_t)c0       * (J * CIN) + iin) * KS + k];
        v.y = weight[((size_t)(c0 + 1) * (J * CIN) + iin) * KS + k];
    }
    g_wp[idx] = v;
}

extern __shared__ float xs[];   // [128][XPITCH] floats = 72 KB

__global__ void __launch_bounds__(NTHREADS)
skel_kernel(const float* __restrict__ x,
            const float* __restrict__ bias,
            float* __restrict__ out)
{
    const int tid = threadIdx.x;
    const int tt  = blockIdx.x;     // time tile
    const int g   = blockIdx.y;     // joint pair / output group
    const int b   = blockIdx.z;     // batch
    const int t0  = tt * TILE_T;

    // ---- load x tile: rows = 4 relative joints * 32 ch, cols = XCOLS frames ----
    const int j0 = 2 * g - 1;       // absolute joint of relative row-group 0
    #pragma unroll 1
    for (int base = 0; base < 128 * XPITCH; base += NTHREADS) {
        int idx = base + tid;
        int row = idx / XPITCH;
        int col = idx - row * XPITCH;
        float v = 0.f;
        if (col < XCOLS) {
            int aj = j0 + (row >> 5);
            int gf = t0 - PAD + col;
            if (aj >= 0 && aj < J && gf >= 0 && gf < TFRAMES)
                v = x[((size_t)b * (J * CIN) + aj * CIN + (row & 31)) * TFRAMES + gf];
        }
        xs[idx] = v;
    }
    __syncthreads();

    // ---- thread mapping: cq(16) x tq(16); thread owns 4 channels x 8 frames ----
    const int cq   = tid & 15;
    const int tq   = tid >> 4;           // 0..15  -> frames [tq*8, tq*8+8)
    const int half = cq >> 3;            // 0: joint 2g, 1: joint 2g+1
    const int cql  = cq & 7;             // channels 4*cql .. 4*cql+3 of that joint
    const int jme  = 2 * g + half;
    const int trel = tq * 8;

    unsigned long long accA[8], accB[8]; // f32x2 packed over channel pairs
    #pragma unroll
    for (int f = 0; f < 8; ++f) { accA[f] = 0ull; accB[f] = 0ull; }

    const float2* wbase = g_wp + (size_t)jme * (3 * 16 * 32 * KS)
                               + (size_t)(2 * cql) * (32 * KS);

    #pragma unroll 1
    for (int s = 0; s < 3; ++s) {
        const float*  xrow = xs + (size_t)((s + half) * 32) * XPITCH + trel;
        const float2* w0s  = wbase + (size_t)s * (16 * 32 * KS);
        #pragma unroll 1
        for (int ci = 0; ci < 32; ++ci) {
            // load 22 input frames once, duplicate into {x,x} pairs
            unsigned long long xd[22];
            const float* xr = xrow + ci * XPITCH;
            #pragma unroll
            for (int u = 0; u < 22; ++u) {
                int vi = __float_as_int(xr[u]);
                asm("mov.b64 %0, {%1, %1};" : "=l"(xd[u]) : "r"(vi));
            }
            const float2* wA = w0s + ci * KS;
            const float2* wB = wA + 32 * KS;
            #pragma unroll
            for (int k = 0; k < KS; ++k) {
                unsigned long long wa = *reinterpret_cast<const unsigned long long*>(wA + k);
                unsigned long long wb = *reinterpret_cast<const unsigned long long*>(wB + k);
                #pragma unroll
                for (int f = 0; f < 8; ++f) {
                    asm("fma.rn.f32x2 %0, %1, %2, %0;" : "+l"(accA[f]) : "l"(wa), "l"(xd[k + f]));
                    asm("fma.rn.f32x2 %0, %1, %2, %0;" : "+l"(accB[f]) : "l"(wb), "l"(xd[k + f]));
                }
            }
        }
    }

    // ---- epilogue: pool joint pair via shfl.xor(8), + bias, LeakyReLU ----
    float bc[4];
    #pragma unroll
    for (int cc = 0; cc < 4; ++cc)
        bc[cc] = 0.5f * (bias[(2 * g)     * COUT + 4 * cql + cc] +
                         bias[(2 * g + 1) * COUT + 4 * cql + cc]);

    float* orow = out + ((size_t)b * (12 * COUT) + g * COUT) * TFRAMES + t0 + trel;

    #pragma unroll
    for (int p = 0; p < 2; ++p) {
        #pragma unroll
        for (int f = 0; f < 8; ++f) {
            unsigned long long a = p ? accB[f] : accA[f];
            int ilo, ihi;
            asm("mov.b64 {%0, %1}, %2;" : "=r"(ilo), "=r"(ihi) : "l"(a));
            float lo = __int_as_float(ilo);
            float hi = __int_as_float(ihi);
            float olo = __shfl_xor_sync(0xffffffffu, lo, 8);
            float ohi = __shfl_xor_sync(0xffffffffu, hi, 8);
            float v0 = 0.5f * (lo + olo) + bc[2 * p];
            float v1 = 0.5f * (hi + ohi) + bc[2 * p + 1];
            v0 = (v0 >= 0.f) ? v0 : 0.2f * v0;
            v1 = (v1 >= 0.f) ? v1 : 0.2f * v1;
            if (half == 0) {
                orow[(size_t)(4 * cql + 2 * p)     * TFRAMES + f] = v0;
                orow[(size_t)(4 * cql + 2 * p + 1) * TFRAMES + f] = v1;
            }
        }
    }
}

extern "C" void kernel_launch(void* const* d_in, const int* in_sizes, int n_in,
                              void* d_out, int out_size) {
    const float* x      = (const float*)d_in[0];  // [32, 768, 4096]
    const float* weight = (const float*)d_in[1];  // [768, 768, 15]
    const float* bias   = (const float*)d_in[2];  // [768]
    // d_in[3] = mask (topology is deterministic; reproduced analytically)
    // d_in[4] = pool_pairs (consecutive pairs; hardcoded)
    float* out = (float*)d_out;                   // [32, 384, 4096]

    const int total = J * 3 * 16 * 32 * KS;
    wprep_kernel<<<(total + 255) / 256, 256>>>(weight);

    const int smem = 128 * XPITCH * sizeof(float);   // 73728 B
    cudaFuncSetAttribute(skel_kernel, cudaFuncAttributeMaxDynamicSharedMemorySize, smem);
    dim3 grid(TFRAMES / TILE_T, 12, BB);
    skel_kernel<<<grid, NTHREADS, smem>>>(x, bias, out);
}

// round 2
// speedup vs baseline: 5.9041x; 5.9041x over previous
#include <cuda_runtime.h>

#define J 24
#define CIN 32
#define COUT 32
#define KS 15
#define PAD 7
#define BB 32
#define TFRAMES 4096
#define TILE_T 128
#define XCOLS 142            // TILE_T + KS - 1
#define XPITCH 144
#define GRP_STRIDE (32 * XPITCH + 8)   // +8 float skew per joint-group: kills half0/half1 bank conflicts
#define NTHREADS 256

// Weights repacked lane-contiguous:
// [g(12)][s(3)][ci(32)][k(15)][cq(16)] float4 = { w[co0], w[co1], w[co2], w[co3] }
// where j = 2g + (cq>>3), co0..3 = 4*(cq&7) .. +3 of joint j, input joint i = j-1+s.
// Zero-filled when i out of range (== topology mask baked in).
__device__ float4 g_wq[12 * 3 * 32 * KS * 16];

__global__ void wprep_kernel(const float* __restrict__ weight) {
    int idx = blockIdx.x * blockDim.x + threadIdx.x;
    const int total = 12 * 3 * 32 * KS * 16;
    if (idx >= total) return;
    int r = idx;
    int cq = r % 16;  r /= 16;
    int k  = r % KS;  r /= KS;
    int ci = r % 32;  r /= 32;
    int s  = r % 3;   r /= 3;
    int g  = r;
    int j   = 2 * g + (cq >> 3);
    int cql = cq & 7;
    int i   = j - 1 + s;
    float4 v = make_float4(0.f, 0.f, 0.f, 0.f);
    if (i >= 0 && i < J) {
        size_t base = ((size_t)(j * COUT + 4 * cql) * (J * CIN) + (i * CIN + ci)) * KS + k;
        const size_t ostr = (size_t)(J * CIN) * KS;
        v.x = weight[base];
        v.y = weight[base + ostr];
        v.z = weight[base + 2 * ostr];
        v.w = weight[base + 3 * ostr];
    }
    g_wq[idx] = v;
}

extern __shared__ float xs[];   // 3*GRP_STRIDE + 32*XPITCH floats = 73,824 B

__global__ void __launch_bounds__(NTHREADS, 2)
skel_kernel(const float* __restrict__ x,
            const float* __restrict__ bias,
            float* __restrict__ out)
{
    const int tid = threadIdx.x;
    const int tt  = blockIdx.x;     // time tile
    const int g   = blockIdx.y;     // joint pair / output group
    const int b   = blockIdx.z;     // batch
    const int t0  = tt * TILE_T;

    // ---- load x tile: 4 relative joints (2g-1..2g+2) x 32 ch x XCOLS frames, skewed per group ----
    const int j0 = 2 * g - 1;
    #pragma unroll 1
    for (int base = 0; base < 128 * XPITCH; base += NTHREADS) {
        int idx = base + tid;
        int row = idx / XPITCH;
        int col = idx - row * XPITCH;
        int grp = row >> 5;
        float v = 0.f;
        if (col < XCOLS) {
            int aj = j0 + grp;
            int gf = t0 - PAD + col;
            if (aj >= 0 && aj < J && gf >= 0 && gf < TFRAMES)
                v = x[((size_t)b * (J * CIN) + aj * CIN + (row & 31)) * TFRAMES + gf];
        }
        xs[grp * GRP_STRIDE + (row & 31) * XPITCH + col] = v;
    }
    __syncthreads();

    // ---- thread mapping: cq(16) x tq(16); thread owns 4 out-channels x 8 frames ----
    const int cq   = tid & 15;
    const int tq   = tid >> 4;           // frames [tq*8, tq*8+8)
    const int half = cq >> 3;            // 0: joint 2g, 1: joint 2g+1
    const int cql  = cq & 7;             // out-channels 4*cql..4*cql+3 of that joint
    const int trel = tq * 8;

    unsigned long long accA[8], accB[8]; // f32x2 packed over channel pairs (co0,co1) / (co2,co3)
    #pragma unroll
    for (int f = 0; f < 8; ++f) { accA[f] = 0ull; accB[f] = 0ull; }

    const float4* wg = g_wq + (size_t)g * (3 * 32 * KS * 16) + cq;

    #pragma unroll 1
    for (int s = 0; s < 3; ++s) {
        const float*  xrow = xs + (s + half) * GRP_STRIDE + trel;
        const float4* ws   = wg + (size_t)s * (32 * KS * 16);
        #pragma unroll 1
        for (int ci = 0; ci < 32; ++ci) {
            // load 24 input frames (6 x LDS.128), duplicate 22 into {x,x} f32x2 pairs
            const float* xr = xrow + ci * XPITCH;
            float xv[24];
            #pragma unroll
            for (int u = 0; u < 6; ++u) {
                float4 t4 = reinterpret_cast<const float4*>(xr)[u];
                xv[4 * u + 0] = t4.x; xv[4 * u + 1] = t4.y;
                xv[4 * u + 2] = t4.z; xv[4 * u + 3] = t4.w;
            }
            unsigned long long xd[22];
            #pragma unroll
            for (int u = 0; u < 22; ++u) {
                int vi = __float_as_int(xv[u]);
                asm("mov.b64 %0, {%1, %1};" : "=l"(xd[u]) : "r"(vi));
            }
            const float4* wp = ws + ci * (KS * 16);
            #pragma unroll
            for (int k = 0; k < KS; ++k) {
                // one LDG.128 = {wA(co0,co1), wB(co2,co3)}; warp lanes contiguous -> 2 wavefronts
                ulonglong2 w2 = *reinterpret_cast<const ulonglong2*>(wp + (size_t)k * 16);
                #pragma unroll
                for (int f = 0; f < 8; ++f) {
                    asm("fma.rn.f32x2 %0, %1, %2, %0;" : "+l"(accA[f]) : "l"(w2.x), "l"(xd[k + f]));
                    asm("fma.rn.f32x2 %0, %1, %2, %0;" : "+l"(accB[f]) : "l"(w2.y), "l"(xd[k + f]));
                }
            }
        }
    }

    // ---- epilogue: pool joint pair via shfl.xor(8), + bias, LeakyReLU ----
    float bc[4];
    #pragma unroll
    for (int cc = 0; cc < 4; ++cc)
        bc[cc] = 0.5f * (bias[(2 * g)     * COUT + 4 * cql + cc] +
                         bias[(2 * g + 1) * COUT + 4 * cql + cc]);

    float* orow = out + ((size_t)b * (12 * COUT) + g * COUT) * TFRAMES + t0 + trel;

    #pragma unroll
    for (int p = 0; p < 2; ++p) {
        #pragma unroll
        for (int f = 0; f < 8; ++f) {
            unsigned long long a = p ? accB[f] : accA[f];
            int ilo, ihi;
            asm("mov.b64 {%0, %1}, %2;" : "=r"(ilo), "=r"(ihi) : "l"(a));
            float lo = __int_as_float(ilo);
            float hi = __int_as_float(ihi);
            float olo = __shfl_xor_sync(0xffffffffu, lo, 8);
            float ohi = __shfl_xor_sync(0xffffffffu, hi, 8);
            float v0 = 0.5f * (lo + olo) + bc[2 * p];
            float v1 = 0.5f * (hi + ohi) + bc[2 * p + 1];
            v0 = (v0 >= 0.f) ? v0 : 0.2f * v0;
            v1 = (v1 >= 0.f) ? v1 : 0.2f * v1;
            if (half == 0) {
                orow[(size_t)(4 * cql + 2 * p)     * TFRAMES + f] = v0;
                orow[(size_t)(4 * cql + 2 * p + 1) * TFRAMES + f] = v1;
            }
        }
    }
}

extern "C" void kernel_launch(void* const* d_in, const int* in_sizes, int n_in,
                              void* d_out, int out_size) {
    const float* x      = (const float*)d_in[0];  // [32, 768, 4096]
    const float* weight = (const float*)d_in[1];  // [768, 768, 15]
    const float* bias   = (const float*)d_in[2];  // [768]
    float* out = (float*)d_out;                   // [32, 384, 4096]

    const int total = 12 * 3 * 32 * KS * 16;
    wprep_kernel<<<(total + 255) / 256, 256>>>(weight);

    const int smem = (3 * GRP_STRIDE + 32 * XPITCH) * sizeof(float);   // 73,824 B
    cudaFuncSetAttribute(skel_kernel, cudaFuncAttributeMaxDynamicSharedMemorySize, smem);
    dim3 grid(TFRAMES / TILE_T, 12, BB);
    skel_kernel<<<grid, NTHREADS, smem>>>(x, bias, out);
}

// round 3
// speedup vs baseline: 6.7585x; 1.1447x over previous
#include <cuda_runtime.h>

#define J 24
#define CIN 32
#define COUT 32
#define KS 15
#define PAD 7
#define BB 32
#define TFRAMES 4096
#define TILE_T 128
#define XPITCH 144           // smem cols; col c <-> frame t0-8+c (full 144 used)
#define GRP_STRIDE (32 * XPITCH + 8)   // +8 float skew per joint-group: kills half0/half1 bank conflicts
#define NTHREADS 256

// Weights repacked lane-contiguous:
// [g(12)][s(3)][ci(32)][k(15)][cq(16)] float4 = { w[co0], w[co1], w[co2], w[co3] }
// where j = 2g + (cq>>3), co0..3 = 4*(cq&7) .. +3 of joint j, input joint i = j-1+s.
// Zero-filled when i out of range (== topology mask baked in).
__device__ float4 g_wq[12 * 3 * 32 * KS * 16];

__global__ void wprep_kernel(const float* __restrict__ weight) {
    int idx = blockIdx.x * blockDim.x + threadIdx.x;
    const int total = 12 * 3 * 32 * KS * 16;
    if (idx >= total) return;
    int r = idx;
    int cq = r % 16;  r /= 16;
    int k  = r % KS;  r /= KS;
    int ci = r % 32;  r /= 32;
    int s  = r % 3;   r /= 3;
    int g  = r;
    int j   = 2 * g + (cq >> 3);
    int cql = cq & 7;
    int i   = j - 1 + s;
    float4 v = make_float4(0.f, 0.f, 0.f, 0.f);
    if (i >= 0 && i < J) {
        size_t base = ((size_t)(j * COUT + 4 * cql) * (J * CIN) + (i * CIN + ci)) * KS + k;
        const size_t ostr = (size_t)(J * CIN) * KS;
        v.x = weight[base];
        v.y = weight[base + ostr];
        v.z = weight[base + 2 * ostr];
        v.w = weight[base + 3 * ostr];
    }
    g_wq[idx] = v;
}

extern __shared__ float xs[];   // 3*GRP_STRIDE + 32*XPITCH floats = 73,824 B

__global__ void __launch_bounds__(NTHREADS, 2)
skel_kernel(const float* __restrict__ x,
            const float* __restrict__ bias,
            float* __restrict__ out)
{
    const int tid = threadIdx.x;
    const int tt  = blockIdx.x;     // time tile
    const int g   = blockIdx.y;     // joint pair / output group
    const int b   = blockIdx.z;     // batch
    const int t0  = tt * TILE_T;

    // ---- load x tile, fully vectorized: smem col c <-> frame t0-8+c ----
    // 128 rows x 36 float4; each 4-frame block is entirely valid or entirely OOB.
    const int j0 = 2 * g - 1;
    #pragma unroll 1
    for (int it = 0; it < (128 * 36) / NTHREADS; ++it) {
        int idx = it * NTHREADS + tid;
        int row = idx / 36;              // const-div -> mul-high
        int u   = idx - row * 36;
        int grp = row >> 5;
        int ch  = row & 31;
        int aj  = j0 + grp;
        int gf  = t0 - 8 + 4 * u;
        float4 v = make_float4(0.f, 0.f, 0.f, 0.f);
        if (aj >= 0 && aj < J && gf >= 0 && gf < TFRAMES)
            v = *reinterpret_cast<const float4*>(
                    &x[((size_t)b * (J * CIN) + aj * CIN + ch) * TFRAMES + gf]);
        *reinterpret_cast<float4*>(&xs[grp * GRP_STRIDE + ch * XPITCH + 4 * u]) = v;
    }
    __syncthreads();

    // ---- thread mapping: cq(16) x tq(16); thread owns 4 out-channels x 8 frames ----
    const int cq   = tid & 15;
    const int tq   = tid >> 4;           // frames [tq*8, tq*8+8)
    const int half = cq >> 3;            // 0: joint 2g, 1: joint 2g+1
    const int cql  = cq & 7;             // out-channels 4*cql..4*cql+3 of that joint
    const int trel = tq * 8;

    unsigned long long accA[8], accB[8]; // f32x2 packed over channel pairs (co0,co1) / (co2,co3)
    #pragma unroll
    for (int f = 0; f < 8; ++f) { accA[f] = 0ull; accB[f] = 0ull; }

    const float4* wg = g_wq + (size_t)g * (3 * 32 * KS * 16) + cq;

    #pragma unroll 1
    for (int s = 0; s < 3; ++s) {
        const float*  xrow = xs + (s + half) * GRP_STRIDE + trel;
        const float4* ws   = wg + (size_t)s * (32 * KS * 16);
        #pragma unroll 1
        for (int ci = 0; ci < 32; ++ci) {
            // 6 x LDS.128 load frames t0-8+trel .. +23; conv needs window offset +1
            const float* xr = xrow + ci * XPITCH;
            float xv[24];
            #pragma unroll
            for (int u = 0; u < 6; ++u) {
                float4 t4 = reinterpret_cast<const float4*>(xr)[u];
                xv[4 * u + 0] = t4.x; xv[4 * u + 1] = t4.y;
                xv[4 * u + 2] = t4.z; xv[4 * u + 3] = t4.w;
            }
            unsigned long long xd[22];
            #pragma unroll
            for (int u = 0; u < 22; ++u) {
                int vi = __float_as_int(xv[u + 1]);   // +1: window shift
                asm("mov.b64 %0, {%1, %1};" : "=l"(xd[u]) : "r"(vi));
            }
            const float4* wp = ws + ci * (KS * 16);
            #pragma unroll
            for (int k = 0; k < KS; ++k) {
                // one LDG.128 = {wA(co0,co1), wB(co2,co3)}; warp lanes contiguous -> 2 wavefronts
                ulonglong2 w2 = *reinterpret_cast<const ulonglong2*>(wp + (size_t)k * 16);
                #pragma unroll
                for (int f = 0; f < 8; ++f) {
                    asm("fma.rn.f32x2 %0, %1, %2, %0;" : "+l"(accA[f]) : "l"(w2.x), "l"(xd[k + f]));
                    asm("fma.rn.f32x2 %0, %1, %2, %0;" : "+l"(accB[f]) : "l"(w2.y), "l"(xd[k + f]));
                }
            }
        }
    }

    // ---- epilogue: pool joint pair via shfl.xor(8), + bias, LeakyReLU, STG.128 ----
    float bc[4];
    #pragma unroll
    for (int cc = 0; cc < 4; ++cc)
        bc[cc] = 0.5f * (bias[(2 * g)     * COUT + 4 * cql + cc] +
                         bias[(2 * g + 1) * COUT + 4 * cql + cc]);

    float* orow = out + ((size_t)b * (12 * COUT) + g * COUT) * TFRAMES + t0 + trel;

    #pragma unroll
    for (int p = 0; p < 2; ++p) {
        float rv0[8], rv1[8];
        #pragma unroll
        for (int f = 0; f < 8; ++f) {
            unsigned long long a = p ? accB[f] : accA[f];
            int ilo, ihi;
            asm("mov.b64 {%0, %1}, %2;" : "=r"(ilo), "=r"(ihi) : "l"(a));
            float lo = __int_as_float(ilo);
            float hi = __int_as_float(ihi);
            float olo = __shfl_xor_sync(0xffffffffu, lo, 8);
            float ohi = __shfl_xor_sync(0xffffffffu, hi, 8);
            float v0 = 0.5f * (lo + olo) + bc[2 * p];
            float v1 = 0.5f * (hi + ohi) + bc[2 * p + 1];
            rv0[f] = (v0 >= 0.f) ? v0 : 0.2f * v0;
            rv1[f] = (v1 >= 0.f) ? v1 : 0.2f * v1;
        }
        if (half == 0) {
            float* b0 = orow + (size_t)(4 * cql + 2 * p)     * TFRAMES;
            float* b1 = orow + (size_t)(4 * cql + 2 * p + 1) * TFRAMES;
            *reinterpret_cast<float4*>(b0)     = make_float4(rv0[0], rv0[1], rv0[2], rv0[3]);
            *reinterpret_cast<float4*>(b0 + 4) = make_float4(rv0[4], rv0[5], rv0[6], rv0[7]);
            *reinterpret_cast<float4*>(b1)     = make_float4(rv1[0], rv1[1], rv1[2], rv1[3]);
            *reinterpret_cast<float4*>(b1 + 4) = make_float4(rv1[4], rv1[5], rv1[6], rv1[7]);
        }
    }
}

extern "C" void kernel_launch(void* const* d_in, const int* in_sizes, int n_in,
                              void* d_out, int out_size) {
    const float* x      = (const float*)d_in[0];  // [32, 768, 4096]
    const float* weight = (const float*)d_in[1];  // [768, 768, 15]
    const float* bias   = (const float*)d_in[2];  // [768]
    float* out = (float*)d_out;                   // [32, 384, 4096]

    const int total = 12 * 3 * 32 * KS * 16;
    wprep_kernel<<<(total + 255) / 256, 256>>>(weight);

    const int smem = (3 * GRP_STRIDE + 32 * XPITCH) * sizeof(float);   // 73,824 B
    cudaFuncSetAttribute(skel_kernel, cudaFuncAttributeMaxDynamicSharedMemorySize, smem);
    dim3 grid(TFRAMES / TILE_T, 12, BB);
    skel_kernel<<<grid, NTHREADS, smem>>>(x, bias, out);
}

// round 5
// speedup vs baseline: 14.9387x; 2.2103x over previous
#include <cuda_runtime.h>
#include <cuda_bf16.h>
#include <cstdint>

#define J 24
#define TFR 4096
#define BB 32
#define KS 15
#define NT 512

// ---- smem layout (bytes) ----
#define A_ROWS   272
#define A_PITCH  256                 // 128 ch * bf16
#define ASZ      (A_ROWS * A_PITCH)  // 69632
#define SMEM_AH  0
#define SMEM_AL  ASZ
#define SMEM_W   (2 * ASZ)           // 139264
#define WTAP     24576               // per-tap W: 2 pass * 2 half * 96ch * 64B
#define SMEM_TOTAL (SMEM_W + 2 * WTAP)   // 188416
#define EPI_PITCH 1040               // 260 f32
#define EPI_HB    33280              // 32 co * EPI_PITCH

// scratch
__device__ __nv_bfloat16 g_xh[(size_t)BB * TFR * 768];
__device__ __nv_bfloat16 g_xl[(size_t)BB * TFR * 768];
__device__ __align__(16) __nv_bfloat16 g_wt[12 * KS * WTAP / 2];

// ---------------- helpers ----------------
__device__ __forceinline__ uint32_t smem_u32(const void* p) {
    uint32_t a;
    asm("{ .reg .u64 t; cvta.to.shared.u64 t, %1; cvt.u32.u64 %0, t; }" : "=r"(a) : "l"(p));
    return a;
}
__device__ __forceinline__ void ldsm_x4(uint32_t* r, uint32_t a) {
    asm volatile("ldmatrix.sync.aligned.m8n8.x4.shared.b16 {%0,%1,%2,%3}, [%4];"
                 : "=r"(r[0]), "=r"(r[1]), "=r"(r[2]), "=r"(r[3]) : "r"(a));
}
__device__ __forceinline__ void ldsm_x4t(uint32_t* r, uint32_t a) {
    asm volatile("ldmatrix.sync.aligned.m8n8.x4.trans.shared.b16 {%0,%1,%2,%3}, [%4];"
                 : "=r"(r[0]), "=r"(r[1]), "=r"(r[2]), "=r"(r[3]) : "r"(a));
}
__device__ __forceinline__ void mma_bf16(float* d, const uint32_t* a, uint32_t b0, uint32_t b1) {
    asm volatile("mma.sync.aligned.m16n8k16.row.col.f32.bf16.bf16.f32 "
                 "{%0,%1,%2,%3}, {%4,%5,%6,%7}, {%8,%9}, {%0,%1,%2,%3};"
                 : "+f"(d[0]), "+f"(d[1]), "+f"(d[2]), "+f"(d[3])
                 : "r"(a[0]), "r"(a[1]), "r"(a[2]), "r"(a[3]), "r"(b0), "r"(b1));
}
__device__ __forceinline__ void cp16(uint32_t dst, const void* src, uint32_t srcsz) {
    asm volatile("cp.async.cg.shared.global [%0], [%1], 16, %2;"
                 :: "r"(dst), "l"(src), "r"(srcsz) : "memory");
}
#define CP_COMMIT() asm volatile("cp.async.commit_group;" ::: "memory")
#define CP_WAIT0()  asm volatile("cp.async.wait_group 0;" ::: "memory")

__device__ __forceinline__ int iclamp(int v, int lo, int hi) {
    return v < lo ? lo : (v > hi ? hi : v);
}

// ---------------- pre-pass: transpose + bf16 hi/lo split of x ----------------
__global__ void xprep(const float* __restrict__ x) {
    __shared__ float sx[32][33];
    int tx = threadIdx.x, ty = threadIdx.y;
    int t0 = blockIdx.x * 32, ch0 = blockIdx.y * 32, b = blockIdx.z;
    #pragma unroll
    for (int i = 0; i < 4; ++i)
        sx[ty + 8 * i][tx] = x[((size_t)b * 768 + ch0 + ty + 8 * i) * TFR + t0 + tx];
    __syncthreads();
    #pragma unroll
    for (int i = 0; i < 4; ++i) {
        int r = ty + 8 * i;
        float f = sx[tx][r];
        __nv_bfloat16 h = __float2bfloat16(f);
        __nv_bfloat16 l = __float2bfloat16(f - __bfloat162float(h));
        size_t o = ((size_t)b * TFR + t0 + r) * 768 + ch0 + tx;
        g_xh[o] = h;  g_xl[o] = l;
    }
}

// ---------------- pre-pass: masked W -> bf16 hi/lo, [ch][n] swizzled ----------------
__global__ void wprep(const float* __restrict__ w) {
    int idx = blockIdx.x * 256 + threadIdx.x;
    const int total = 12 * KS * 2 * 2 * 96 * 32;
    if (idx >= total) return;
    int n = idx & 31;         idx >>= 5;
    int r = idx % 96;         idx /= 96;
    int h = idx & 1;          idx >>= 1;
    int p = idx & 1;          idx >>= 1;
    int k = idx % KS;
    int g = idx / KS;
    int jb = iclamp(2 * g - 1, 0, J - 4);
    int sj = iclamp(2 * g - 1 + h, jb, jb + 1);
    int ji = sj + (r >> 5), ci = r & 31;
    int j  = 2 * g + h;
    float v = 0.f;
    int d = ji - j;
    if (d >= -1 && d <= 1)
        v = w[((size_t)(j * 32 + n) * 768 + (size_t)(ji * 32 + ci)) * KS + k];
    __nv_bfloat16 hv = __float2bfloat16(v);
    __nv_bfloat16 ov = p ? __float2bfloat16(v - __bfloat162float(hv)) : hv;
    size_t off = (size_t)(g * KS + k) * WTAP + p * 12288 + h * 6144
               + r * 64 + ((((uint32_t)n >> 3) ^ ((r >> 1) & 3)) << 4) + (n & 7) * 2;
    *reinterpret_cast<__nv_bfloat16*>(reinterpret_cast<char*>(g_wt) + off) = ov;
}

// ---------------- main: mma.sync conv ----------------
__global__ void __launch_bounds__(NT)
skel_mma(const float* __restrict__ bias, float* __restrict__ out)
{
    extern __shared__ char smem[];
    const uint32_t sb = smem_u32(smem);
    const int tid = threadIdx.x;
    const int l = tid & 31, w = tid >> 5;
    const int mq = w >> 1, h = w & 1;
    const int tt = blockIdx.x, g = blockIdx.y, b = blockIdx.z;
    const int t0 = tt * 256;

    const int jb = iclamp(2 * g - 1, 0, J - 4);
    const int sj = iclamp(2 * g - 1 + h, jb, jb + 1);
    const int cb = (sj - jb) * 4;           // A chunk base for this half
    const size_t chb = (size_t)jb * 32;     // x channel base (4-joint union)

    // ---- prologue: cp.async A tiles (hi+lo, zfill OOB) + W tap0 ----
    #pragma unroll 1
    for (int it = 0; it < 17; ++it) {
        int i = it * NT + tid;              // 0..8703
        int hl = i >= 4352;
        int ii = i - hl * 4352;
        int r = ii >> 4, u = ii & 15;
        int t = t0 - 8 + r;
        uint32_t ok = (t >= 0 && t < TFR) ? 16u : 0u;
        uint32_t dst = sb + hl * ASZ + r * A_PITCH + (((uint32_t)(u ^ (r & 7))) << 4);
        const __nv_bfloat16* src = (hl ? g_xl : g_xh)
            + (((size_t)b * TFR + t) * 768 + chb + (size_t)u * 8);
        cp16(dst, src, ok);
    }
    {
        const char* wsrc = reinterpret_cast<const char*>(g_wt) + (size_t)(g * KS) * WTAP;
        #pragma unroll
        for (int c = 0; c < 3; ++c) {
            int i = c * NT + tid;           // 0..1535
            cp16(sb + SMEM_W + i * 16, wsrc + (size_t)i * 16, 16u);
        }
    }
    CP_COMMIT();

    // per-lane constants
    const int row_off = (l & 7) + ((l >> 3) & 1) * 8;
    const int ca      = (l >> 4) & 1;
    const int bswz    = (row_off >> 1) & 3;
    const uint32_t b_lane0 = row_off * 64 + ((uint32_t)((0 + ca) ^ bswz) << 4);
    const uint32_t b_lane1 = row_off * 64 + ((uint32_t)((2 + ca) ^ bswz) << 4);

    float acc[2][4][4];
    #pragma unroll
    for (int mi = 0; mi < 2; ++mi)
        #pragma unroll
        for (int jf = 0; jf < 4; ++jf)
            #pragma unroll
            for (int e = 0; e < 4; ++e) acc[mi][jf][e] = 0.f;

    #pragma unroll 1
    for (int k = 0; k < KS; ++k) {
        CP_WAIT0();
        __syncthreads();
        if (k + 1 < KS) {   // prefetch next tap into other stage
            const char* wsrc = reinterpret_cast<const char*>(g_wt) + (size_t)(g * KS + k + 1) * WTAP;
            uint32_t wdst = sb + SMEM_W + ((k + 1) & 1) * WTAP;
            #pragma unroll
            for (int c = 0; c < 3; ++c) {
                int i = c * NT + tid;
                cp16(wdst + i * 16, wsrc + (size_t)i * 16, 16u);
            }
            CP_COMMIT();
        }
        const uint32_t bst = sb + SMEM_W + (k & 1) * WTAP + h * 6144;

        #pragma unroll 1
        for (int q = 0; q < 6; ++q) {
            uint32_t ah[2][4], al[2][4];
            #pragma unroll
            for (int mi = 0; mi < 2; ++mi) {
                int row = mq * 32 + mi * 16 + row_off + k + 1;
                uint32_t aaddr = sb + row * A_PITCH
                    + ((uint32_t)((cb + 2 * q + ca) ^ (row & 7)) << 4);
                ldsm_x4(ah[mi], aaddr);
                ldsm_x4(al[mi], aaddr + ASZ);
            }
            uint32_t bhf[8], blf[8];
            {
                uint32_t base = bst + q * 1024;
                ldsm_x4t(bhf,     base + b_lane0);
                ldsm_x4t(bhf + 4, base + b_lane1);
                ldsm_x4t(blf,     base + 12288 + b_lane0);
                ldsm_x4t(blf + 4, base + 12288 + b_lane1);
            }
            #pragma unroll
            for (int mi = 0; mi < 2; ++mi)
                #pragma unroll
                for (int jf = 0; jf < 4; ++jf) {
                    float* d = acc[mi][jf];
                    mma_bf16(d, ah[mi], bhf[2 * jf], bhf[2 * jf + 1]);
                    mma_bf16(d, ah[mi], blf[2 * jf], blf[2 * jf + 1]);
                    mma_bf16(d, al[mi], bhf[2 * jf], bhf[2 * jf + 1]);
                }
        }
    }

    // ---- epilogue: dump to smem (reuse A region), pool halves, bias+leaky ----
    __syncthreads();
    #pragma unroll
    for (int mi = 0; mi < 2; ++mi)
        #pragma unroll
        for (int jf = 0; jf < 4; ++jf)
            #pragma unroll
            for (int e = 0; e < 4; ++e) {
                int co = 8 * jf + 2 * (l & 3) + (e & 1);
                int fr = mq * 32 + mi * 16 + (l >> 2) + 8 * (e >> 1);
                *reinterpret_cast<float*>(smem + h * EPI_HB + co * EPI_PITCH + fr * 4)
                    = acc[mi][jf][e];
            }
    __syncthreads();

    {
        int co = tid >> 4;
        int fs = (tid & 15) * 16;
        float bsum = 0.5f * (bias[g * 64 + co] + bias[g * 64 + 32 + co]);
        float* obase = out + ((size_t)b * 384 + g * 32 + co) * TFR + t0 + fs;
        #pragma unroll
        for (int u = 0; u < 4; ++u) {
            float4 v0 = *reinterpret_cast<float4*>(smem + co * EPI_PITCH + (fs + 4 * u) * 4);
            float4 v1 = *reinterpret_cast<float4*>(smem + EPI_HB + co * EPI_PITCH + (fs + 4 * u) * 4);
            float4 r;
            r.x = 0.5f * (v0.x + v1.x) + bsum;
            r.y = 0.5f * (v0.y + v1.y) + bsum;
            r.z = 0.5f * (v0.z + v1.z) + bsum;
            r.w = 0.5f * (v0.w + v1.w) + bsum;
            r.x = (r.x >= 0.f) ? r.x : 0.2f * r.x;
            r.y = (r.y >= 0.f) ? r.y : 0.2f * r.y;
            r.z = (r.z >= 0.f) ? r.z : 0.2f * r.z;
            r.w = (r.w >= 0.f) ? r.w : 0.2f * r.w;
            *reinterpret_cast<float4*>(obase + 4 * u) = r;
        }
    }
}

extern "C" void kernel_launch(void* const* d_in, const int* in_sizes, int n_in,
                              void* d_out, int out_size) {
    const float* x      = (const float*)d_in[0];  // [32, 768, 4096]
    const float* weight = (const float*)d_in[1];  // [768, 768, 15]
    const float* bias   = (const float*)d_in[2];  // [768]
    float* out = (float*)d_out;                   // [32, 384, 4096]

    dim3 tb(32, 8);
    dim3 tg(TFR / 32, 768 / 32, BB);
    xprep<<<tg, tb>>>(x);

    const int wtotal = 12 * KS * 2 * 2 * 96 * 32;
    wprep<<<(wtotal + 255) / 256, 256>>>(weight);

    cudaFuncSetAttribute(skel_mma, cudaFuncAttributeMaxDynamicSharedMemorySize, SMEM_TOTAL);
    dim3 grid(TFR / 256, 12, BB);
    skel_mma<<<grid, NT, SMEM_TOTAL>>>(bias, out);
}

// round 6
// speedup vs baseline: 19.5756x; 1.3104x over previous
#include <cuda_runtime.h>
#include <cuda_fp16.h>
#include <cstdint>

#define J 24
#define TFR 4096
#define BB 32
#define KS 15
#define NT 512

// ---- smem layout (bytes) ----
#define A_ROWS   272
#define A_PITCH  256                 // 128 ch * fp16
#define ASZ      (A_ROWS * A_PITCH)  // 69632
#define SMEM_W   (2 * ASZ)           // 139264
#define WTAP     12288               // per-tap W: 2 half * 96ch * 64B (single fp16 pass)
#define SMEM_TOTAL (SMEM_W + 2 * WTAP)   // 163840
#define EPI_PITCH 1040               // 260 f32
#define EPI_HB    33280              // 32 co * EPI_PITCH

// scratch
__device__ __half g_xh[(size_t)BB * TFR * 768];
__device__ __half g_xl[(size_t)BB * TFR * 768];
__device__ __align__(16) __half g_wt[12 * KS * WTAP / 2];

// ---------------- helpers ----------------
__device__ __forceinline__ uint32_t smem_u32(const void* p) {
    uint32_t a;
    asm("{ .reg .u64 t; cvta.to.shared.u64 t, %1; cvt.u32.u64 %0, t; }" : "=r"(a) : "l"(p));
    return a;
}
__device__ __forceinline__ void ldsm_x4(uint32_t* r, uint32_t a) {
    asm volatile("ldmatrix.sync.aligned.m8n8.x4.shared.b16 {%0,%1,%2,%3}, [%4];"
                 : "=r"(r[0]), "=r"(r[1]), "=r"(r[2]), "=r"(r[3]) : "r"(a));
}
__device__ __forceinline__ void ldsm_x4t(uint32_t* r, uint32_t a) {
    asm volatile("ldmatrix.sync.aligned.m8n8.x4.trans.shared.b16 {%0,%1,%2,%3}, [%4];"
                 : "=r"(r[0]), "=r"(r[1]), "=r"(r[2]), "=r"(r[3]) : "r"(a));
}
__device__ __forceinline__ void mma_f16(float* d, const uint32_t* a, uint32_t b0, uint32_t b1) {
    asm volatile("mma.sync.aligned.m16n8k16.row.col.f32.f16.f16.f32 "
                 "{%0,%1,%2,%3}, {%4,%5,%6,%7}, {%8,%9}, {%0,%1,%2,%3};"
                 : "+f"(d[0]), "+f"(d[1]), "+f"(d[2]), "+f"(d[3])
                 : "r"(a[0]), "r"(a[1]), "r"(a[2]), "r"(a[3]), "r"(b0), "r"(b1));
}
__device__ __forceinline__ void cp16(uint32_t dst, const void* src, uint32_t srcsz) {
    asm volatile("cp.async.cg.shared.global [%0], [%1], 16, %2;"
                 :: "r"(dst), "l"(src), "r"(srcsz) : "memory");
}
#define CP_COMMIT() asm volatile("cp.async.commit_group;" ::: "memory")
#define CP_WAIT0()  asm volatile("cp.async.wait_group 0;" ::: "memory")

__device__ __forceinline__ int iclamp(int v, int lo, int hi) {
    return v < lo ? lo : (v > hi ? hi : v);
}

// ---------------- pre-pass: transpose + fp16 hi/lo split of x ----------------
__global__ void xprep(const float* __restrict__ x) {
    __shared__ float sx[32][33];
    int tx = threadIdx.x, ty = threadIdx.y;
    int t0 = blockIdx.x * 32, ch0 = blockIdx.y * 32, b = blockIdx.z;
    #pragma unroll
    for (int i = 0; i < 4; ++i)
        sx[ty + 8 * i][tx] = x[((size_t)b * 768 + ch0 + ty + 8 * i) * TFR + t0 + tx];
    __syncthreads();
    #pragma unroll
    for (int i = 0; i < 4; ++i) {
        int r = ty + 8 * i;
        float f = sx[tx][r];
        __half h = __float2half_rn(f);
        __half l = __float2half_rn(f - __half2float(h));
        size_t o = ((size_t)b * TFR + t0 + r) * 768 + ch0 + tx;
        g_xh[o] = h;  g_xl[o] = l;
    }
}

// ---------------- pre-pass: masked W -> fp16, [ch][n] swizzled ----------------
__global__ void wprep(const float* __restrict__ w) {
    int idx = blockIdx.x * 256 + threadIdx.x;
    const int total = 12 * KS * 2 * 96 * 32;
    if (idx >= total) return;
    int n = idx & 31;         idx >>= 5;
    int r = idx % 96;         idx /= 96;
    int h = idx & 1;          idx >>= 1;
    int k = idx % KS;
    int g = idx / KS;
    int jb = iclamp(2 * g - 1, 0, J - 4);
    int sj = iclamp(2 * g - 1 + h, jb, jb + 1);
    int ji = sj + (r >> 5), ci = r & 31;
    int j  = 2 * g + h;
    float v = 0.f;
    int d = ji - j;
    if (d >= -1 && d <= 1)
        v = w[((size_t)(j * 32 + n) * 768 + (size_t)(ji * 32 + ci)) * KS + k];
    size_t off = (size_t)(g * KS + k) * WTAP + h * 6144
               + r * 64 + ((((uint32_t)n >> 3) ^ ((r >> 1) & 3)) << 4) + (n & 7) * 2;
    *reinterpret_cast<__half*>(reinterpret_cast<char*>(g_wt) + off) = __float2half_rn(v);
}

// ---------------- main: mma.sync conv, fp16 2-pass ----------------
__global__ void __launch_bounds__(NT)
skel_mma(const float* __restrict__ bias, float* __restrict__ out)
{
    extern __shared__ char smem[];
    const uint32_t sb = smem_u32(smem);
    const int tid = threadIdx.x;
    const int l = tid & 31, w = tid >> 5;
    const int mq = w >> 1, h = w & 1;
    const int tt = blockIdx.x, g = blockIdx.y, b = blockIdx.z;
    const int t0 = tt * 256;

    const int jb = iclamp(2 * g - 1, 0, J - 4);
    const int sj = iclamp(2 * g - 1 + h, jb, jb + 1);
    const int cb = (sj - jb) * 4;           // A chunk base for this half
    const size_t chb = (size_t)jb * 32;     // x channel base (4-joint union)

    // ---- prologue: cp.async A tiles (hi+lo, zfill OOB) + W tap0 ----
    #pragma unroll 1
    for (int it = 0; it < 17; ++it) {
        int i = it * NT + tid;              // 0..8703
        int hl = i >= 4352;
        int ii = i - hl * 4352;
        int r = ii >> 4, u = ii & 15;
        int t = t0 - 8 + r;
        uint32_t ok = (t >= 0 && t < TFR) ? 16u : 0u;
        uint32_t dst = sb + hl * ASZ + r * A_PITCH + (((uint32_t)(u ^ (r & 7))) << 4);
        const __half* src = (hl ? g_xl : g_xh)
            + (((size_t)b * TFR + t) * 768 + chb + (size_t)u * 8);
        cp16(dst, src, ok);
    }
    {
        const char* wsrc = reinterpret_cast<const char*>(g_wt) + (size_t)(g * KS) * WTAP;
        #pragma unroll
        for (int c = 0; c < 2; ++c) {
            int i = c * NT + tid;           // 0..1023, need 768
            if (i < WTAP / 16)
                cp16(sb + SMEM_W + i * 16, wsrc + (size_t)i * 16, 16u);
        }
    }
    CP_COMMIT();

    // per-lane constants
    const int row_off = (l & 7) + ((l >> 3) & 1) * 8;
    const int ca      = (l >> 4) & 1;
    const int bswz    = (row_off >> 1) & 3;
    const uint32_t b_lane0 = row_off * 64 + ((uint32_t)((0 + ca) ^ bswz) << 4);
    const uint32_t b_lane1 = row_off * 64 + ((uint32_t)((2 + ca) ^ bswz) << 4);

    float acc[2][4][4];
    #pragma unroll
    for (int mi = 0; mi < 2; ++mi)
        #pragma unroll
        for (int jf = 0; jf < 4; ++jf)
            #pragma unroll
            for (int e = 0; e < 4; ++e) acc[mi][jf][e] = 0.f;

    #pragma unroll 1
    for (int k = 0; k < KS; ++k) {
        CP_WAIT0();
        __syncthreads();
        if (k + 1 < KS) {   // prefetch next tap into other stage
            const char* wsrc = reinterpret_cast<const char*>(g_wt) + (size_t)(g * KS + k + 1) * WTAP;
            uint32_t wdst = sb + SMEM_W + ((k + 1) & 1) * WTAP;
            #pragma unroll
            for (int c = 0; c < 2; ++c) {
                int i = c * NT + tid;
                if (i < WTAP / 16)
                    cp16(wdst + i * 16, wsrc + (size_t)i * 16, 16u);
            }
            CP_COMMIT();
        }
        const uint32_t bst = sb + SMEM_W + (k & 1) * WTAP + h * 6144;

        #pragma unroll 1
        for (int q = 0; q < 6; ++q) {
            uint32_t ah[2][4], al[2][4];
            #pragma unroll
            for (int mi = 0; mi < 2; ++mi) {
                int row = mq * 32 + mi * 16 + row_off + k + 1;
                uint32_t aaddr = sb + row * A_PITCH
                    + ((uint32_t)((cb + 2 * q + ca) ^ (row & 7)) << 4);
                ldsm_x4(ah[mi], aaddr);
                ldsm_x4(al[mi], aaddr + ASZ);
            }
            uint32_t bf[8];
            {
                uint32_t base = bst + q * 1024;
                ldsm_x4t(bf,     base + b_lane0);
                ldsm_x4t(bf + 4, base + b_lane1);
            }
            #pragma unroll
            for (int mi = 0; mi < 2; ++mi)
                #pragma unroll
                for (int jf = 0; jf < 4; ++jf) {
                    float* d = acc[mi][jf];
                    mma_f16(d, ah[mi], bf[2 * jf], bf[2 * jf + 1]);
                    mma_f16(d, al[mi], bf[2 * jf], bf[2 * jf + 1]);
                }
        }
    }

    // ---- epilogue: dump to smem (reuse A region), pool halves, bias+leaky ----
    __syncthreads();
    #pragma unroll
    for (int mi = 0; mi < 2; ++mi)
        #pragma unroll
        for (int jf = 0; jf < 4; ++jf)
            #pragma unroll
            for (int e = 0; e < 4; ++e) {
                int co = 8 * jf + 2 * (l & 3) + (e & 1);
                int fr = mq * 32 + mi * 16 + (l >> 2) + 8 * (e >> 1);
                *reinterpret_cast<float*>(smem + h * EPI_HB + co * EPI_PITCH + fr * 4)
                    = acc[mi][jf][e];
            }
    __syncthreads();

    {
        int co = tid >> 4;
        int fs = (tid & 15) * 16;
        float bsum = 0.5f * (bias[g * 64 + co] + bias[g * 64 + 32 + co]);
        float* obase = out + ((size_t)b * 384 + g * 32 + co) * TFR + t0 + fs;
        #pragma unroll
        for (int u = 0; u < 4; ++u) {
            float4 v0 = *reinterpret_cast<float4*>(smem + co * EPI_PITCH + (fs + 4 * u) * 4);
            float4 v1 = *reinterpret_cast<float4*>(smem + EPI_HB + co * EPI_PITCH + (fs + 4 * u) * 4);
            float4 r;
            r.x = 0.5f * (v0.x + v1.x) + bsum;
            r.y = 0.5f * (v0.y + v1.y) + bsum;
            r.z = 0.5f * (v0.z + v1.z) + bsum;
            r.w = 0.5f * (v0.w + v1.w) + bsum;
            r.x = (r.x >= 0.f) ? r.x : 0.2f * r.x;
            r.y = (r.y >= 0.f) ? r.y : 0.2f * r.y;
            r.z = (r.z >= 0.f) ? r.z : 0.2f * r.z;
            r.w = (r.w >= 0.f) ? r.w : 0.2f * r.w;
            *reinterpret_cast<float4*>(obase + 4 * u) = r;
        }
    }
}

extern "C" void kernel_launch(void* const* d_in, const int* in_sizes, int n_in,
                              void* d_out, int out_size) {
    const float* x      = (const float*)d_in[0];  // [32, 768, 4096]
    const float* weight = (const float*)d_in[1];  // [768, 768, 15]
    const float* bias   = (const float*)d_in[2];  // [768]
    float* out = (float*)d_out;                   // [32, 384, 4096]

    dim3 tb(32, 8);
    dim3 tg(TFR / 32, 768 / 32, BB);
    xprep<<<tg, tb>>>(x);

    const int wtotal = 12 * KS * 2 * 96 * 32;
    wprep<<<(wtotal + 255) / 256, 256>>>(weight);

    cudaFuncSetAttribute(skel_mma, cudaFuncAttributeMaxDynamicSharedMemorySize, SMEM_TOTAL);
    dim3 grid(TFR / 256, 12, BB);
    skel_mma<<<grid, NT, SMEM_TOTAL>>>(bias, out);
}

// round 8
// speedup vs baseline: 35.4245x; 1.8096x over previous
#include <cuda_runtime.h>
#include <cuda_fp16.h>
#include <cstdint>

#define J 24
#define TFR 4096
#define BB 32
#define KS 15
#define NT 512

// ---- smem layout (bytes) ----
#define A_ROWS   272
#define A_PITCH  256                 // 128 ch * fp16
#define ASZ      (A_ROWS * A_PITCH)  // 69632
#define SMEM_W   ASZ                 // 69632
#define WTAP     12288               // per-tap W: 2 half * 96ch * 64B
#define SMEM_TOTAL (SMEM_W + 2 * WTAP)   // 94208 -> 2 CTAs/SM
#define EPI_PITCH 1040               // 260 f32
#define EPI_HB    33280              // 32 co * EPI_PITCH

// scratch
__device__ __half g_x[(size_t)BB * TFR * 768];
__device__ __align__(16) __half g_wt[12 * KS * WTAP / 2];

// ---------------- helpers ----------------
__device__ __forceinline__ uint32_t smem_u32(const void* p) {
    uint32_t a;
    asm("{ .reg .u64 t; cvta.to.shared.u64 t, %1; cvt.u32.u64 %0, t; }" : "=r"(a) : "l"(p));
    return a;
}
__device__ __forceinline__ void ldsm_x4(uint32_t* r, uint32_t a) {
    asm volatile("ldmatrix.sync.aligned.m8n8.x4.shared.b16 {%0,%1,%2,%3}, [%4];"
                 : "=r"(r[0]), "=r"(r[1]), "=r"(r[2]), "=r"(r[3]) : "r"(a));
}
__device__ __forceinline__ void ldsm_x4t(uint32_t* r, uint32_t a) {
    asm volatile("ldmatrix.sync.aligned.m8n8.x4.trans.shared.b16 {%0,%1,%2,%3}, [%4];"
                 : "=r"(r[0]), "=r"(r[1]), "=r"(r[2]), "=r"(r[3]) : "r"(a));
}
__device__ __forceinline__ void mma_f16(float* d, const uint32_t* a, uint32_t b0, uint32_t b1) {
    asm volatile("mma.sync.aligned.m16n8k16.row.col.f32.f16.f16.f32 "
                 "{%0,%1,%2,%3}, {%4,%5,%6,%7}, {%8,%9}, {%0,%1,%2,%3};"
                 : "+f"(d[0]), "+f"(d[1]), "+f"(d[2]), "+f"(d[3])
                 : "r"(a[0]), "r"(a[1]), "r"(a[2]), "r"(a[3]), "r"(b0), "r"(b1));
}
__device__ __forceinline__ void cp16(uint32_t dst, const void* src, uint32_t srcsz) {
    asm volatile("cp.async.cg.shared.global [%0], [%1], 16, %2;"
                 :: "r"(dst), "l"(src), "r"(srcsz) : "memory");
}
#define CP_COMMIT() asm volatile("cp.async.commit_group;" ::: "memory")
#define CP_WAIT0()  asm volatile("cp.async.wait_group 0;" ::: "memory")

__device__ __forceinline__ int iclamp(int v, int lo, int hi) {
    return v < lo ? lo : (v > hi ? hi : v);
}

// ---------------- pre-pass: transpose x -> fp16 [b][t][ch] ----------------
__global__ void xprep(const float* __restrict__ x) {
    __shared__ float sx[32][33];
    int tx = threadIdx.x, ty = threadIdx.y;
    int t0 = blockIdx.x * 32, ch0 = blockIdx.y * 32, b = blockIdx.z;
    #pragma unroll
    for (int i = 0; i < 4; ++i)
        sx[ty + 8 * i][tx] = x[((size_t)b * 768 + ch0 + ty + 8 * i) * TFR + t0 + tx];
    __syncthreads();
    #pragma unroll
    for (int i = 0; i < 4; ++i) {
        int r = ty + 8 * i;
        g_x[((size_t)b * TFR + t0 + r) * 768 + ch0 + tx] = __float2half_rn(sx[tx][r]);
    }
}

// ---------------- pre-pass: masked W -> fp16, [ch][n] swizzled ----------------
__global__ void wprep(const float* __restrict__ w) {
    int idx = blockIdx.x * 256 + threadIdx.x;
    const int total = 12 * KS * 2 * 96 * 32;
    if (idx >= total) return;
    int n = idx & 31;         idx >>= 5;
    int r = idx % 96;         idx /= 96;
    int h = idx & 1;          idx >>= 1;
    int k = idx % KS;
    int g = idx / KS;
    int jb = iclamp(2 * g - 1, 0, J - 4);
    int sj = iclamp(2 * g - 1 + h, jb, jb + 1);
    int ji = sj + (r >> 5), ci = r & 31;
    int j  = 2 * g + h;
    float v = 0.f;
    int d = ji - j;
    if (d >= -1 && d <= 1)
        v = w[((size_t)(j * 32 + n) * 768 + (size_t)(ji * 32 + ci)) * KS + k];
    size_t off = (size_t)(g * KS + k) * WTAP + h * 6144
               + r * 64 + ((((uint32_t)n >> 3) ^ ((r >> 1) & 3)) << 4) + (n & 7) * 2;
    *reinterpret_cast<__half*>(reinterpret_cast<char*>(g_wt) + off) = __float2half_rn(v);
}

// ---------------- main: mma.sync conv, fp16 single-pass ----------------
__global__ void __launch_bounds__(NT, 2)
skel_mma(const float* __restrict__ bias, float* __restrict__ out)
{
    extern __shared__ char smem[];
    const uint32_t sb = smem_u32(smem);
    const int tid = threadIdx.x;
    const int l = tid & 31, w = tid >> 5;
    const int mq = w >> 1, h = w & 1;
    const int tt = blockIdx.x, g = blockIdx.y, b = blockIdx.z;
    const int t0 = tt * 256;

    const int jb = iclamp(2 * g - 1, 0, J - 4);
    const int sj = iclamp(2 * g - 1 + h, jb, jb + 1);
    const int cb = (sj - jb) * 4;           // A chunk base for this half
    const size_t chb = (size_t)jb * 32;     // x channel base (4-joint union)

    // ---- prologue: cp.async A tile (zfill OOB) + W tap0 ----
    #pragma unroll 1
    for (int it = 0; it < 9; ++it) {
        int i = it * NT + tid;              // need 0..4351
        if (i < 4352) {
            int r = i >> 4, u = i & 15;
            int t = t0 - 8 + r;
            uint32_t ok = (t >= 0 && t < TFR) ? 16u : 0u;
            uint32_t dst = sb + r * A_PITCH + (((uint32_t)(u ^ (r & 7))) << 4);
            const __half* src = g_x + (((size_t)b * TFR + t) * 768 + chb + (size_t)u * 8);
            cp16(dst, src, ok);
        }
    }
    {
        const char* wsrc = reinterpret_cast<const char*>(g_wt) + (size_t)(g * KS) * WTAP;
        #pragma unroll
        for (int c = 0; c < 2; ++c) {
            int i = c * NT + tid;           // need 0..767
            if (i < WTAP / 16)
                cp16(sb + SMEM_W + i * 16, wsrc + (size_t)i * 16, 16u);
        }
    }
    CP_COMMIT();

    // per-lane constants
    const int row_off = (l & 7) + ((l >> 3) & 1) * 8;
    const int ca      = (l >> 4) & 1;
    const int bswz    = (row_off >> 1) & 3;
    const uint32_t b_lane0 = row_off * 64 + ((uint32_t)((0 + ca) ^ bswz) << 4);
    const uint32_t b_lane1 = row_off * 64 + ((uint32_t)((2 + ca) ^ bswz) << 4);

    float acc[2][4][4];
    #pragma unroll
    for (int mi = 0; mi < 2; ++mi)
        #pragma unroll
        for (int jf = 0; jf < 4; ++jf)
            #pragma unroll
            for (int e = 0; e < 4; ++e) acc[mi][jf][e] = 0.f;

    #pragma unroll 1
    for (int k = 0; k < KS; ++k) {
        CP_WAIT0();
        __syncthreads();
        if (k + 1 < KS) {   // prefetch next tap into other stage
            const char* wsrc = reinterpret_cast<const char*>(g_wt) + (size_t)(g * KS + k + 1) * WTAP;
            uint32_t wdst = sb + SMEM_W + ((k + 1) & 1) * WTAP;
            #pragma unroll
            for (int c = 0; c < 2; ++c) {
                int i = c * NT + tid;
                if (i < WTAP / 16)
                    cp16(wdst + i * 16, wsrc + (size_t)i * 16, 16u);
            }
            CP_COMMIT();
        }
        const uint32_t bst = sb + SMEM_W + (k & 1) * WTAP + h * 6144;

        #pragma unroll 1
        for (int q = 0; q < 6; ++q) {
            uint32_t ah[2][4];
            #pragma unroll
            for (int mi = 0; mi < 2; ++mi) {
                int row = mq * 32 + mi * 16 + row_off + k + 1;
                uint32_t aaddr = sb + row * A_PITCH
                    + ((uint32_t)((cb + 2 * q + ca) ^ (row & 7)) << 4);
                ldsm_x4(ah[mi], aaddr);
            }
            uint32_t bf[8];
            {
                uint32_t base = bst + q * 1024;
                ldsm_x4t(bf,     base + b_lane0);
                ldsm_x4t(bf + 4, base + b_lane1);
            }
            #pragma unroll
            for (int mi = 0; mi < 2; ++mi)
                #pragma unroll
                for (int jf = 0; jf < 4; ++jf)
                    mma_f16(acc[mi][jf], ah[mi], bf[2 * jf], bf[2 * jf + 1]);
        }
    }

    // ---- epilogue: dump to smem (reuse A region), pool halves, bias+leaky ----
    __syncthreads();
    #pragma unroll
    for (int mi = 0; mi < 2; ++mi)
        #pragma unroll
        for (int jf = 0; jf < 4; ++jf)
            #pragma unroll
            for (int e = 0; e < 4; ++e) {
                int co = 8 * jf + 2 * (l & 3) + (e & 1);
                int fr = mq * 32 + mi * 16 + (l >> 2) + 8 * (e >> 1);
                *reinterpret_cast<float*>(smem + h * EPI_HB + co * EPI_PITCH + fr * 4)
                    = acc[mi][jf][e];
            }
    __syncthreads();

    {
        int co = tid >> 4;
        int fs = (tid & 15) * 16;
        float bsum = 0.5f * (bias[g * 64 + co] + bias[g * 64 + 32 + co]);
        float* obase = out + ((size_t)b * 384 + g * 32 + co) * TFR + t0 + fs;
        #pragma unroll
        for (int u = 0; u < 4; ++u) {
            float4 v0 = *reinterpret_cast<float4*>(smem + co * EPI_PITCH + (fs + 4 * u) * 4);
            float4 v1 = *reinterpret_cast<float4*>(smem + EPI_HB + co * EPI_PITCH + (fs + 4 * u) * 4);
            float4 r;
            r.x = 0.5f * (v0.x + v1.x) + bsum;
            r.y = 0.5f * (v0.y + v1.y) + bsum;
            r.z = 0.5f * (v0.z + v1.z) + bsum;
            r.w = 0.5f * (v0.w + v1.w) + bsum;
            r.x = (r.x >= 0.f) ? r.x : 0.2f * r.x;
            r.y = (r.y >= 0.f) ? r.y : 0.2f * r.y;
            r.z = (r.z >= 0.f) ? r.z : 0.2f * r.z;
            r.w = (r.w >= 0.f) ? r.w : 0.2f * r.w;
            *reinterpret_cast<float4*>(obase + 4 * u) = r;
        }
    }
}

extern "C" void kernel_launch(void* const* d_in, const int* in_sizes, int n_in,
                              void* d_out, int out_size) {
    const float* x      = (const float*)d_in[0];  // [32, 768, 4096]
    const float* weight = (const float*)d_in[1];  // [768, 768, 15]
    const float* bias   = (const float*)d_in[2];  // [768]
    float* out = (float*)d_out;                   // [32, 384, 4096]

    dim3 tb(32, 8);
    dim3 tg(TFR / 32, 768 / 32, BB);
    xprep<<<tg, tb>>>(x);

    const int wtotal = 12 * KS * 2 * 96 * 32;
    wprep<<<(wtotal + 255) / 256, 256>>>(weight);

    cudaFuncSetAttribute(skel_mma, cudaFuncAttributeMaxDynamicSharedMemorySize, SMEM_TOTAL);
    dim3 grid(TFR / 256, 12, BB);
    skel_mma<<<grid, NT, SMEM_TOTAL>>>(bias, out);
}

// round 9
// speedup vs baseline: 37.1629x; 1.0491x over previous
#include <cuda_runtime.h>
#include <cuda_fp16.h>
#include <cstdint>

#define J 24
#define TFR 4096
#define BB 32
#define KS 15
#define NT 256

// ---- smem layout (bytes) ----
#define A_ROWS   272
#define A_PITCH  256                 // 128 ch * fp16
#define ASZ      (A_ROWS * A_PITCH)  // 69632
#define SMEM_W   ASZ                 // 69632
#define WTAP     12288               // per-tap W: 2 half * 96ch * 64B
#define SMEM_TOTAL (SMEM_W + 2 * WTAP)   // 94208 -> 2 CTAs/SM
#define EPI_PITCH 1040               // 260 f32
#define EPI_HB    33280              // 32 co * EPI_PITCH

// scratch
__device__ __half g_x[(size_t)BB * TFR * 768];
__device__ __align__(16) __half g_wt[12 * KS * WTAP / 2];

// ---------------- helpers ----------------
__device__ __forceinline__ uint32_t smem_u32(const void* p) {
    uint32_t a;
    asm("{ .reg .u64 t; cvta.to.shared.u64 t, %1; cvt.u32.u64 %0, t; }" : "=r"(a) : "l"(p));
    return a;
}
__device__ __forceinline__ void ldsm_x4(uint32_t* r, uint32_t a) {
    asm volatile("ldmatrix.sync.aligned.m8n8.x4.shared.b16 {%0,%1,%2,%3}, [%4];"
                 : "=r"(r[0]), "=r"(r[1]), "=r"(r[2]), "=r"(r[3]) : "r"(a));
}
__device__ __forceinline__ void ldsm_x4t(uint32_t* r, uint32_t a) {
    asm volatile("ldmatrix.sync.aligned.m8n8.x4.trans.shared.b16 {%0,%1,%2,%3}, [%4];"
                 : "=r"(r[0]), "=r"(r[1]), "=r"(r[2]), "=r"(r[3]) : "r"(a));
}
__device__ __forceinline__ void mma_f16(float* d, const uint32_t* a, uint32_t b0, uint32_t b1) {
    asm volatile("mma.sync.aligned.m16n8k16.row.col.f32.f16.f16.f32 "
                 "{%0,%1,%2,%3}, {%4,%5,%6,%7}, {%8,%9}, {%0,%1,%2,%3};"
                 : "+f"(d[0]), "+f"(d[1]), "+f"(d[2]), "+f"(d[3])
                 : "r"(a[0]), "r"(a[1]), "r"(a[2]), "r"(a[3]), "r"(b0), "r"(b1));
}
__device__ __forceinline__ void cp16(uint32_t dst, const void* src, uint32_t srcsz) {
    asm volatile("cp.async.cg.shared.global [%0], [%1], 16, %2;"
                 :: "r"(dst), "l"(src), "r"(srcsz) : "memory");
}
#define CP_COMMIT() asm volatile("cp.async.commit_group;" ::: "memory")
#define CP_WAIT0()  asm volatile("cp.async.wait_group 0;" ::: "memory")

__device__ __forceinline__ int iclamp(int v, int lo, int hi) {
    return v < lo ? lo : (v > hi ? hi : v);
}

// ---------------- pre-pass: transpose x -> fp16 [b][t][ch], vectorized ----------------
__global__ void xprep(const float* __restrict__ x) {
    __shared__ float sx[64][65];
    const int tid = threadIdx.x;                 // 256 threads
    const int t0 = blockIdx.x * 64, ch0 = blockIdx.y * 64, b = blockIdx.z;
    // load 64 ch rows x 64 t via float4
    {
        const int row = tid >> 4;                // 0..15
        const int v   = tid & 15;                // float4 index
        #pragma unroll
        for (int pp = 0; pp < 4; ++pp) {
            const int r = pp * 16 + row;
            float4 f = *reinterpret_cast<const float4*>(
                &x[((size_t)b * 768 + ch0 + r) * TFR + t0 + 4 * v]);
            sx[r][4 * v + 0] = f.x;  sx[r][4 * v + 1] = f.y;
            sx[r][4 * v + 2] = f.z;  sx[r][4 * v + 3] = f.w;
        }
    }
    __syncthreads();
    // write 64 t rows x 64 ch via half2 (128 B per warp-row)
    {
        const int lane = tid & 31;               // ch pair
        const int rowq = tid >> 5;               // 0..7
        #pragma unroll
        for (int pp = 0; pp < 8; ++pp) {
            const int tr = pp * 8 + rowq;
            __half2 hv = __floats2half2_rn(sx[2 * lane][tr], sx[2 * lane + 1][tr]);
            *reinterpret_cast<__half2*>(
                &g_x[((size_t)b * TFR + t0 + tr) * 768 + ch0 + 2 * lane]) = hv;
        }
    }
}

// ---------------- pre-pass: masked W -> fp16, [ch][n] swizzled ----------------
__global__ void wprep(const float* __restrict__ w) {
    int idx = blockIdx.x * 256 + threadIdx.x;
    const int total = 12 * KS * 2 * 96 * 32;
    if (idx >= total) return;
    int n = idx & 31;         idx >>= 5;
    int r = idx % 96;         idx /= 96;
    int h = idx & 1;          idx >>= 1;
    int k = idx % KS;
    int g = idx / KS;
    int jb = iclamp(2 * g - 1, 0, J - 4);
    int sj = iclamp(2 * g - 1 + h, jb, jb + 1);
    int ji = sj + (r >> 5), ci = r & 31;
    int j  = 2 * g + h;
    float v = 0.f;
    int d = ji - j;
    if (d >= -1 && d <= 1)
        v = w[((size_t)(j * 32 + n) * 768 + (size_t)(ji * 32 + ci)) * KS + k];
    size_t off = (size_t)(g * KS + k) * WTAP + h * 6144
               + r * 64 + ((((uint32_t)n >> 3) ^ ((r >> 1) & 3)) << 4) + (n & 7) * 2;
    *reinterpret_cast<__half*>(reinterpret_cast<char*>(g_wt) + off) = __float2half_rn(v);
}

// ---------------- main: mma.sync conv, fp16 single-pass, M=64/warp ----------------
__global__ void __launch_bounds__(NT, 2)
skel_mma(const float* __restrict__ bias, float* __restrict__ out)
{
    extern __shared__ char smem[];
    const uint32_t sb = smem_u32(smem);
    const int tid = threadIdx.x;
    const int l = tid & 31, w = tid >> 5;
    const int mq = w >> 1, h = w & 1;       // mq 0..3: frames [mq*64, mq*64+64)
    const int tt = blockIdx.x, g = blockIdx.y, b = blockIdx.z;
    const int t0 = tt * 256;

    const int jb = iclamp(2 * g - 1, 0, J - 4);
    const int sj = iclamp(2 * g - 1 + h, jb, jb + 1);
    const int cb = (sj - jb) * 4;           // A chunk base for this half
    const size_t chb = (size_t)jb * 32;     // x channel base (4-joint union)

    // ---- prologue: cp.async A tile (zfill OOB) + W tap0 ----
    #pragma unroll 1
    for (int it = 0; it < 17; ++it) {
        int i = it * NT + tid;              // 0..4351
        int r = i >> 4, u = i & 15;
        int t = t0 - 8 + r;
        uint32_t ok = (t >= 0 && t < TFR) ? 16u : 0u;
        uint32_t dst = sb + r * A_PITCH + (((uint32_t)(u ^ (r & 7))) << 4);
        const __half* src = g_x + (((size_t)b * TFR + t) * 768 + chb + (size_t)u * 8);
        cp16(dst, src, ok);
    }
    {
        const char* wsrc = reinterpret_cast<const char*>(g_wt) + (size_t)(g * KS) * WTAP;
        #pragma unroll
        for (int c = 0; c < 3; ++c) {
            int i = c * NT + tid;           // 0..767
            cp16(sb + SMEM_W + i * 16, wsrc + (size_t)i * 16, 16u);
        }
    }
    CP_COMMIT();

    // per-lane constants
    const int row_off = (l & 7) + ((l >> 3) & 1) * 8;
    const int ca      = (l >> 4) & 1;
    const int bswz    = (row_off >> 1) & 3;
    const uint32_t b_lane0 = row_off * 64 + ((uint32_t)((0 + ca) ^ bswz) << 4);
    const uint32_t b_lane1 = row_off * 64 + ((uint32_t)((2 + ca) ^ bswz) << 4);

    float acc[4][4][4];
    #pragma unroll
    for (int mi = 0; mi < 4; ++mi)
        #pragma unroll
        for (int jf = 0; jf < 4; ++jf)
            #pragma unroll
            for (int e = 0; e < 4; ++e) acc[mi][jf][e] = 0.f;

    #pragma unroll 1
    for (int k = 0; k < KS; ++k) {
        CP_WAIT0();
        __syncthreads();
        if (k + 1 < KS) {   // prefetch next tap into other stage
            const char* wsrc = reinterpret_cast<const char*>(g_wt) + (size_t)(g * KS + k + 1) * WTAP;
            uint32_t wdst = sb + SMEM_W + ((k + 1) & 1) * WTAP;
            #pragma unroll
            for (int c = 0; c < 3; ++c) {
                int i = c * NT + tid;
                cp16(wdst + i * 16, wsrc + (size_t)i * 16, 16u);
            }
            CP_COMMIT();
        }
        const uint32_t bst = sb + SMEM_W + (k & 1) * WTAP + h * 6144;

        #pragma unroll 1
        for (int q = 0; q < 6; ++q) {
            uint32_t bf[8];
            {
                uint32_t base = bst + q * 1024;
                ldsm_x4t(bf,     base + b_lane0);
                ldsm_x4t(bf + 4, base + b_lane1);
            }
            #pragma unroll
            for (int mi = 0; mi < 4; ++mi) {
                uint32_t ah[4];
                int row = mq * 64 + mi * 16 + row_off + k + 1;
                uint32_t aaddr = sb + row * A_PITCH
                    + ((uint32_t)((cb + 2 * q + ca) ^ (row & 7)) << 4);
                ldsm_x4(ah, aaddr);
                #pragma unroll
                for (int jf = 0; jf < 4; ++jf)
                    mma_f16(acc[mi][jf], ah, bf[2 * jf], bf[2 * jf + 1]);
            }
        }
    }

    // ---- epilogue: dump to smem (reuse A region), pool halves, bias+leaky ----
    __syncthreads();
    #pragma unroll
    for (int mi = 0; mi < 4; ++mi)
        #pragma unroll
        for (int jf = 0; jf < 4; ++jf)
            #pragma unroll
            for (int e = 0; e < 4; ++e) {
                int co = 8 * jf + 2 * (l & 3) + (e & 1);
                int fr = mq * 64 + mi * 16 + (l >> 2) + 8 * (e >> 1);
                *reinterpret_cast<float*>(smem + h * EPI_HB + co * EPI_PITCH + fr * 4)
                    = acc[mi][jf][e];
            }
    __syncthreads();

    {
        int co = tid >> 3;                  // 0..31
        int fs = (tid & 7) * 32;            // 32 frames per thread
        float bsum = 0.5f * (bias[g * 64 + co] + bias[g * 64 + 32 + co]);
        float* obase = out + ((size_t)b * 384 + g * 32 + co) * TFR + t0 + fs;
        #pragma unroll
        for (int u = 0; u < 8; ++u) {
            float4 v0 = *reinterpret_cast<float4*>(smem + co * EPI_PITCH + (fs + 4 * u) * 4);
            float4 v1 = *reinterpret_cast<float4*>(smem + EPI_HB + co * EPI_PITCH + (fs + 4 * u) * 4);
            float4 r;
            r.x = 0.5f * (v0.x + v1.x) + bsum;
            r.y = 0.5f * (v0.y + v1.y) + bsum;
            r.z = 0.5f * (v0.z + v1.z) + bsum;
            r.w = 0.5f * (v0.w + v1.w) + bsum;
            r.x = (r.x >= 0.f) ? r.x : 0.2f * r.x;
            r.y = (r.y >= 0.f) ? r.y : 0.2f * r.y;
            r.z = (r.z >= 0.f) ? r.z : 0.2f * r.z;
            r.w = (r.w >= 0.f) ? r.w : 0.2f * r.w;
            *reinterpret_cast<float4*>(obase + 4 * u) = r;
        }
    }
}

extern "C" void kernel_launch(void* const* d_in, const int* in_sizes, int n_in,
                              void* d_out, int out_size) {
    const float* x      = (const float*)d_in[0];  // [32, 768, 4096]
    const float* weight = (const float*)d_in[1];  // [768, 768, 15]
    const float* bias   = (const float*)d_in[2];  // [768]
    float* out = (float*)d_out;                   // [32, 384, 4096]

    dim3 tg(TFR / 64, 768 / 64, BB);
    xprep<<<tg, 256>>>(x);

    const int wtotal = 12 * KS * 2 * 96 * 32;
    wprep<<<(wtotal + 255) / 256, 256>>>(weight);

    cudaFuncSetAttribute(skel_mma, cudaFuncAttributeMaxDynamicSharedMemorySize, SMEM_TOTAL);
    dim3 grid(TFR / 256, 12, BB);
    skel_mma<<<grid, NT, SMEM_TOTAL>>>(bias, out);
}

// round 10
// speedup vs baseline: 49.6071x; 1.3349x over previous
#include <cuda_runtime.h>
#include <cuda_fp16.h>
#include <cstdint>

#define J 24
#define TFR 4096
#define BB 32
#define KS 15
#define NT 256

// ---- smem layout (bytes) ----
#define A_ROWS   272
#define A_PITCH  256                 // 128 ch * fp16
#define ASZ      (A_ROWS * A_PITCH)  // 69632
#define SMEM_W   ASZ                 // 69632
#define WT       8192                // per-tap pooled W: 128ch x 32n x fp16
#define SMEM_TOTAL (SMEM_W + 4 * WT)     // 102400 -> 2 CTAs/SM
#define EPI_PITCH 1040               // 260 f32

// scratch
__device__ __half g_x[(size_t)BB * TFR * 768];
__device__ __align__(16) __half g_wt[12 * KS * WT / 2];

// ---------------- helpers ----------------
__device__ __forceinline__ uint32_t smem_u32(const void* p) {
    uint32_t a;
    asm("{ .reg .u64 t; cvta.to.shared.u64 t, %1; cvt.u32.u64 %0, t; }" : "=r"(a) : "l"(p));
    return a;
}
__device__ __forceinline__ void ldsm_x4(uint32_t* r, uint32_t a) {
    asm volatile("ldmatrix.sync.aligned.m8n8.x4.shared.b16 {%0,%1,%2,%3}, [%4];"
                 : "=r"(r[0]), "=r"(r[1]), "=r"(r[2]), "=r"(r[3]) : "r"(a));
}
__device__ __forceinline__ void ldsm_x4t(uint32_t* r, uint32_t a) {
    asm volatile("ldmatrix.sync.aligned.m8n8.x4.trans.shared.b16 {%0,%1,%2,%3}, [%4];"
                 : "=r"(r[0]), "=r"(r[1]), "=r"(r[2]), "=r"(r[3]) : "r"(a));
}
__device__ __forceinline__ void mma_f16(float* d, const uint32_t* a, uint32_t b0, uint32_t b1) {
    asm volatile("mma.sync.aligned.m16n8k16.row.col.f32.f16.f16.f32 "
                 "{%0,%1,%2,%3}, {%4,%5,%6,%7}, {%8,%9}, {%0,%1,%2,%3};"
                 : "+f"(d[0]), "+f"(d[1]), "+f"(d[2]), "+f"(d[3])
                 : "r"(a[0]), "r"(a[1]), "r"(a[2]), "r"(a[3]), "r"(b0), "r"(b1));
}
__device__ __forceinline__ void cp16(uint32_t dst, const void* src, uint32_t srcsz) {
    asm volatile("cp.async.cg.shared.global [%0], [%1], 16, %2;"
                 :: "r"(dst), "l"(src), "r"(srcsz) : "memory");
}
#define CP_COMMIT() asm volatile("cp.async.commit_group;" ::: "memory")
#define CP_WAIT0()  asm volatile("cp.async.wait_group 0;" ::: "memory")

__device__ __forceinline__ int iclamp(int v, int lo, int hi) {
    return v < lo ? lo : (v > hi ? hi : v);
}

// ---------------- pre-pass: transpose x -> fp16 [b][t][ch], vectorized ----------------
__global__ void xprep(const float* __restrict__ x) {
    __shared__ float sx[64][65];
    const int tid = threadIdx.x;                 // 256 threads
    const int t0 = blockIdx.x * 64, ch0 = blockIdx.y * 64, b = blockIdx.z;
    {
        const int row = tid >> 4;
        const int v   = tid & 15;
        #pragma unroll
        for (int pp = 0; pp < 4; ++pp) {
            const int r = pp * 16 + row;
            float4 f = *reinterpret_cast<const float4*>(
                &x[((size_t)b * 768 + ch0 + r) * TFR + t0 + 4 * v]);
            sx[r][4 * v + 0] = f.x;  sx[r][4 * v + 1] = f.y;
            sx[r][4 * v + 2] = f.z;  sx[r][4 * v + 3] = f.w;
        }
    }
    __syncthreads();
    {
        const int lane = tid & 31;
        const int rowq = tid >> 5;
        #pragma unroll
        for (int pp = 0; pp < 8; ++pp) {
            const int tr = pp * 8 + rowq;
            __half2 hv = __floats2half2_rn(sx[2 * lane][tr], sx[2 * lane + 1][tr]);
            *reinterpret_cast<__half2*>(
                &g_x[((size_t)b * TFR + t0 + tr) * 768 + ch0 + 2 * lane]) = hv;
        }
    }
}

// ---------------- pre-pass: pooled masked W -> fp16, [ch][n] swizzled ----------------
// W_pool[g][k][ch(128 union)][n(32)] = 0.5 * sum_h mask * w[(2g+h)*32+n][union_ch][k]
__global__ void wprep(const float* __restrict__ w) {
    int idx = blockIdx.x * 256 + threadIdx.x;
    const int total = 12 * KS * 128 * 32;
    if (idx >= total) return;
    int n = idx & 31;         idx >>= 5;
    int r = idx & 127;        idx >>= 7;
    int k = idx % KS;
    int g = idx / KS;
    int jb = iclamp(2 * g - 1, 0, J - 4);
    int ji = jb + (r >> 5), ci = r & 31;
    float v = 0.f;
    #pragma unroll
    for (int h = 0; h < 2; ++h) {
        int j = 2 * g + h;
        int d = ji - j;
        if (d >= -1 && d <= 1)
            v += 0.5f * w[((size_t)(j * 32 + n) * 768 + (size_t)(ji * 32 + ci)) * KS + k];
    }
    size_t off = (size_t)(g * KS + k) * WT
               + r * 64 + ((((uint32_t)n >> 3) ^ ((r >> 1) & 3)) << 4) + (n & 7) * 2;
    *reinterpret_cast<__half*>(reinterpret_cast<char*>(g_wt) + off) = __float2half_rn(v);
}

// ---------------- main: mma.sync pooled conv, fp16, N=32/K=128 ----------------
__global__ void __launch_bounds__(NT, 2)
skel_mma(const float* __restrict__ bias, float* __restrict__ out)
{
    extern __shared__ char smem[];
    const uint32_t sb = smem_u32(smem);
    const int tid = threadIdx.x;
    const int l = tid & 31, wrp = tid >> 5;   // warp owns frames [wrp*32, wrp*32+32)
    const int tt = blockIdx.x, g = blockIdx.y, b = blockIdx.z;
    const int t0 = tt * 256;

    const int jb = iclamp(2 * g - 1, 0, J - 4);
    const size_t chb = (size_t)jb * 32;       // x channel base (4-joint union)

    // ---- prologue: cp.async A tile (zfill OOB) + W taps 0..3 ----
    #pragma unroll 1
    for (int it = 0; it < 17; ++it) {
        int i = it * NT + tid;                // 0..4351
        int r = i >> 4, u = i & 15;
        int t = t0 - 8 + r;
        uint32_t ok = (t >= 0 && t < TFR) ? 16u : 0u;
        uint32_t dst = sb + r * A_PITCH + (((uint32_t)(u ^ (r & 7))) << 4);
        const __half* src = g_x + (((size_t)b * TFR + t) * 768 + chb + (size_t)u * 8);
        cp16(dst, src, ok);
    }
    #pragma unroll
    for (int kk = 0; kk < 4; ++kk) {
        const char* wsrc = reinterpret_cast<const char*>(g_wt) + (size_t)(g * KS + kk) * WT;
        uint32_t wdst = sb + SMEM_W + kk * WT;
        #pragma unroll
        for (int c = 0; c < 2; ++c) {
            int i = c * NT + tid;             // 0..511
            cp16(wdst + i * 16, wsrc + (size_t)i * 16, 16u);
        }
    }
    CP_COMMIT();

    // per-lane constants
    const int row_off = (l & 7) + ((l >> 3) & 1) * 8;
    const int ca      = (l >> 4) & 1;
    const int bswz    = (row_off >> 1) & 3;
    const uint32_t b_lane0 = row_off * 64 + ((uint32_t)((0 + ca) ^ bswz) << 4);
    const uint32_t b_lane1 = row_off * 64 + ((uint32_t)((2 + ca) ^ bswz) << 4);

    float acc[2][4][4];
    #pragma unroll
    for (int mi = 0; mi < 2; ++mi)
        #pragma unroll
        for (int jf = 0; jf < 4; ++jf)
            #pragma unroll
            for (int e = 0; e < 4; ++e) acc[mi][jf][e] = 0.f;

    // ---- tap loop: 2 taps per sync, 4-stage W ring ----
    #pragma unroll 1
    for (int k = 0; k < KS; k += 2) {
        CP_WAIT0();
        __syncthreads();
        #pragma unroll
        for (int d = 2; d < 4; ++d) {
            int kk = k + d;
            if (kk < KS) {
                const char* wsrc = reinterpret_cast<const char*>(g_wt) + (size_t)(g * KS + kk) * WT;
                uint32_t wdst = sb + SMEM_W + (kk & 3) * WT;
                #pragma unroll
                for (int c = 0; c < 2; ++c) {
                    int i = c * NT + tid;
                    cp16(wdst + i * 16, wsrc + (size_t)i * 16, 16u);
                }
            }
        }
        CP_COMMIT();

        #pragma unroll 1
        for (int d = 0; d < 2; ++d) {
            int kk = k + d;
            if (kk >= KS) break;
            const uint32_t bst = sb + SMEM_W + (kk & 3) * WT;
            #pragma unroll
            for (int q = 0; q < 8; ++q) {
                uint32_t bf[8];
                ldsm_x4t(bf,     bst + q * 1024 + b_lane0);
                ldsm_x4t(bf + 4, bst + q * 1024 + b_lane1);
                #pragma unroll
                for (int mi = 0; mi < 2; ++mi) {
                    uint32_t ah[4];
                    int row = wrp * 32 + mi * 16 + row_off + kk + 1;
                    uint32_t aaddr = sb + row * A_PITCH
                        + ((uint32_t)((2 * q + ca) ^ (row & 7)) << 4);
                    ldsm_x4(ah, aaddr);
                    #pragma unroll
                    for (int jf = 0; jf < 4; ++jf)
                        mma_f16(acc[mi][jf], ah, bf[2 * jf], bf[2 * jf + 1]);
                }
            }
        }
    }

    // ---- epilogue: transpose through smem, bias + LeakyReLU, STG.128 ----
    __syncthreads();
    #pragma unroll
    for (int mi = 0; mi < 2; ++mi)
        #pragma unroll
        for (int jf = 0; jf < 4; ++jf)
            #pragma unroll
            for (int e = 0; e < 4; ++e) {
                int co = 8 * jf + 2 * (l & 3) + (e & 1);
                int fr = wrp * 32 + mi * 16 + (l >> 2) + 8 * (e >> 1);
                *reinterpret_cast<float*>(smem + co * EPI_PITCH + fr * 4) = acc[mi][jf][e];
            }
    __syncthreads();

    {
        int co = tid >> 3;                  // 0..31
        int fs = (tid & 7) * 32;            // 32 frames per thread
        float bsum = 0.5f * (bias[g * 64 + co] + bias[g * 64 + 32 + co]);
        float* obase = out + ((size_t)b * 384 + g * 32 + co) * TFR + t0 + fs;
        #pragma unroll
        for (int u = 0; u < 8; ++u) {
            float4 v = *reinterpret_cast<float4*>(smem + co * EPI_PITCH + (fs + 4 * u) * 4);
            float4 r;
            r.x = v.x + bsum;  r.y = v.y + bsum;
            r.z = v.z + bsum;  r.w = v.w + bsum;
            r.x = (r.x >= 0.f) ? r.x : 0.2f * r.x;
            r.y = (r.y >= 0.f) ? r.y : 0.2f * r.y;
            r.z = (r.z >= 0.f) ? r.z : 0.2f * r.z;
            r.w = (r.w >= 0.f) ? r.w : 0.2f * r.w;
            *reinterpret_cast<float4*>(obase + 4 * u) = r;
        }
    }
}

extern "C" void kernel_launch(void* const* d_in, const int* in_sizes, int n_in,
                              void* d_out, int out_size) {
    const float* x      = (const float*)d_in[0];  // [32, 768, 4096]
    const float* weight = (const float*)d_in[1];  // [768, 768, 15]
    const float* bias   = (const float*)d_in[2];  // [768]
    float* out = (float*)d_out;                   // [32, 384, 4096]

    dim3 tg(TFR / 64, 768 / 64, BB);
    xprep<<<tg, 256>>>(x);

    const int wtotal = 12 * KS * 128 * 32;
    wprep<<<(wtotal + 255) / 256, 256>>>(weight);

    cudaFuncSetAttribute(skel_mma, cudaFuncAttributeMaxDynamicSharedMemorySize, SMEM_TOTAL);
    dim3 grid(TFR / 256, 12, BB);
    skel_mma<<<grid, NT, SMEM_TOTAL>>>(bias, out);
}